// round 15
// baseline (speedup 1.0000x reference)
#include <cuda_runtime.h>
#include <cuda_bf16.h>
#include <stdint.h>
#include <math.h>

#define BATCH 16
#define SEQ   2048
#define DIM   512

// ---- scratch (static device globals; allocation-free per harness rules) ----
__device__ __nv_bfloat16 g_Mb[DIM * DIM];              // (Wq Wk^T)^T in bf16
__device__ __nv_bfloat16 g_Tb[BATCH * SEQ * DIM];      // (x*M) in bf16
__device__ __nv_bfloat16 g_xb[BATCH * SEQ * DIM];      // x in bf16
__device__ __nv_bfloat16 g_E[(size_t)BATCH * SEQ * SEQ];  // exp(scores), bf16
__device__ float g_rowsum[BATCH * SEQ];
__device__ float g_rowinv[BATCH * SEQ];
__device__ float g_colsum[BATCH * SEQ];
__device__ float g_y[BATCH * DIM];

// ---- helpers ---------------------------------------------------------------
__device__ __forceinline__ void mma16bf(float c[4], const uint32_t a[4],
                                        uint32_t b0, uint32_t b1) {
    asm volatile(
        "mma.sync.aligned.m16n8k16.row.col.f32.bf16.bf16.f32 "
        "{%0,%1,%2,%3}, {%4,%5,%6,%7}, {%8,%9}, {%0,%1,%2,%3};"
        : "+f"(c[0]), "+f"(c[1]), "+f"(c[2]), "+f"(c[3])
        : "r"(a[0]), "r"(a[1]), "r"(a[2]), "r"(a[3]), "r"(b0), "r"(b1));
}
__device__ __forceinline__ void ldsm4(uint32_t* r, uint32_t addr) {
    asm volatile("ldmatrix.sync.aligned.m8n8.x4.shared.b16 {%0,%1,%2,%3}, [%4];"
        : "=r"(r[0]), "=r"(r[1]), "=r"(r[2]), "=r"(r[3]) : "r"(addr));
}
__device__ __forceinline__ void cp16(uint32_t s, const void* g) {
    asm volatile("cp.async.cg.shared.global [%0], [%1], 16;"
        :: "r"(s), "l"(g) : "memory");
}
__device__ __forceinline__ uint32_t smem_u32(const void* p) {
    uint32_t a;
    asm("{ .reg .u64 t; cvta.to.shared.u64 t, %1; cvt.u32.u64 %0, t; }"
        : "=r"(a) : "l"(p));
    return a;
}

// ============================================================================
// BF16 NT GEMM mainloop: 128x128 CTA tile, BK=64 bf16 (8 chunks of DIM=512),
// 3-stage cp.async, ldmatrix fragments, m16n8k16.
// smem tile: 128 rows x 64 bf16 (128B); soff = row*128 + ((ks ^ (row&7))<<4)
// ============================================================================
#define TILE_H   16384
#define STAGE_H  (2 * TILE_H)
#define SMEM_H   (3 * STAGE_H)   // 96 KB -> 2 CTAs/SM
#define NCH_H    (DIM / 64)      // 8

__device__ __forceinline__ void issue_tile_h(uint32_t sA, uint32_t sB,
    const __nv_bfloat16* __restrict__ gA, const __nv_bfloat16* __restrict__ gB,
    int tid)
{
    #pragma unroll
    for (int c = 0; c < 4; ++c) {
        int lin = c * 256 + tid;
        int row = lin >> 3, ks = lin & 7;
        uint32_t so = (uint32_t)(row * 128 + ((ks ^ (row & 7)) << 4));
        cp16(sA + so, gA + (size_t)row * DIM + ks * 8);
        cp16(sB + so, gB + (size_t)row * DIM + ks * 8);
    }
}

__device__ __forceinline__ void bf16_mainloop(
    uint32_t sb, const __nv_bfloat16* __restrict__ Ab,
    const __nv_bfloat16* __restrict__ Bb,
    int tid, int lane, int wrow, int wcol, float c[4][4][4])
{
    const int local = lane & 7;
    const int rhalf = (lane >> 3) & 1;   // row-half within 16
    const int kof   = lane >> 4;         // kseg offset (0/1)
    uint32_t arow[4]; int asw[4];
    #pragma unroll
    for (int mt = 0; mt < 4; ++mt) {
        int r = wrow + mt * 16 + rhalf * 8 + local;
        arow[mt] = (uint32_t)(r * 128); asw[mt] = r & 7;
    }
    uint32_t brow[2]; int bsw[2];
    #pragma unroll
    for (int bn = 0; bn < 2; ++bn) {
        int r = wcol + bn * 16 + rhalf * 8 + local;
        brow[bn] = (uint32_t)(r * 128); bsw[bn] = r & 7;
    }

    issue_tile_h(sb, sb + TILE_H, Ab, Bb, tid);
    asm volatile("cp.async.commit_group;" ::: "memory");
    issue_tile_h(sb + STAGE_H, sb + STAGE_H + TILE_H, Ab + 64, Bb + 64, tid);
    asm volatile("cp.async.commit_group;" ::: "memory");

    for (int ci = 0; ci < NCH_H; ++ci) {
        if (ci < NCH_H - 1)
            asm volatile("cp.async.wait_group 1;" ::: "memory");
        else
            asm volatile("cp.async.wait_group 0;" ::: "memory");
        __syncthreads();

        if (ci + 2 < NCH_H) {
            uint32_t st = sb + (uint32_t)(((ci + 2) % 3) * STAGE_H);
            issue_tile_h(st, st + TILE_H, Ab + (ci + 2) * 64, Bb + (ci + 2) * 64, tid);
            asm volatile("cp.async.commit_group;" ::: "memory");
        }

        const uint32_t Abase = sb + (uint32_t)((ci % 3) * STAGE_H);
        const uint32_t Bbase = Abase + TILE_H;
        #pragma unroll
        for (int ks = 0; ks < 4; ++ks) {          // 4 k16-steps per BK=64
            const int kseg = ks * 2 + kof;
            uint32_t a[4][4], b[2][4];
            #pragma unroll
            for (int mt = 0; mt < 4; ++mt)
                ldsm4(a[mt], Abase + arow[mt] +
                      (uint32_t)(((kseg ^ asw[mt])) << 4));
            #pragma unroll
            for (int bn = 0; bn < 2; ++bn)
                ldsm4(b[bn], Bbase + brow[bn] +
                      (uint32_t)(((kseg ^ bsw[bn])) << 4));
            #pragma unroll
            for (int nt = 0; nt < 4; ++nt) {
                const int bn = nt >> 1, h = nt & 1;
                #pragma unroll
                for (int mt = 0; mt < 4; ++mt)
                    mma16bf(c[mt][nt], a[mt], b[bn][h], b[bn][h + 2]);
            }
        }
    }
}

// ============================================================================
// Tb = xb * Mb^T (bf16 in, fp32 accum, bf16 out). grid = (DIM/128, M/128)
// ============================================================================
__global__ __launch_bounds__(256, 2) void bf16_nt_bf16out(
    const __nv_bfloat16* __restrict__ A, const __nv_bfloat16* __restrict__ B,
    __nv_bfloat16* __restrict__ C)
{
    extern __shared__ char smem[];
    const uint32_t sb = smem_u32(smem);
    const int tid = threadIdx.x, lane = tid & 31, warp = tid >> 5;
    const int wrow = (warp >> 2) * 64, wcol = (warp & 3) * 32;
    const int crow = blockIdx.y * 128, ccol = blockIdx.x * 128;

    float c[4][4][4] = {};
    bf16_mainloop(sb, A + (size_t)crow * DIM, B + (size_t)ccol * DIM,
                  tid, lane, wrow, wcol, c);

    const int r0 = crow + wrow + (lane >> 2);
    const int c0 = ccol + wcol + (lane & 3) * 2;
    #pragma unroll
    for (int mt = 0; mt < 4; ++mt) {
        #pragma unroll
        for (int nt = 0; nt < 4; ++nt) {
            *(__nv_bfloat162*)(C + (size_t)(r0 + mt * 16) * DIM + c0 + nt * 8) =
                __floats2bfloat162_rn(c[mt][nt][0], c[mt][nt][1]);
            *(__nv_bfloat162*)(C + (size_t)(r0 + mt * 16 + 8) * DIM + c0 + nt * 8) =
                __floats2bfloat162_rn(c[mt][nt][2], c[mt][nt][3]);
        }
    }
}

// ============================================================================
// Scores GEMM + fused exp epilogue:
//   E[b][n][m] = exp(alpha * Tb[b][n]·xb[b][m])  (bf16), rowsum atomics.
// grid = (SEQ/128, SEQ/128, BATCH)
// ============================================================================
__global__ __launch_bounds__(256, 2) void bf16_nt_exp(
    const __nv_bfloat16* __restrict__ A, const __nv_bfloat16* __restrict__ B,
    __nv_bfloat16* __restrict__ E, float* __restrict__ rowsum, float alpha)
{
    extern __shared__ char smem[];
    const uint32_t sb = smem_u32(smem);
    const int tid = threadIdx.x, lane = tid & 31, warp = tid >> 5;
    const int wrow = (warp >> 2) * 64, wcol = (warp & 3) * 32;
    const int z = blockIdx.z;
    const int crow = blockIdx.y * 128, ccol = blockIdx.x * 128;

    float c[4][4][4] = {};
    bf16_mainloop(sb,
                  A + (size_t)z * SEQ * DIM + (size_t)crow * DIM,
                  B + (size_t)z * SEQ * DIM + (size_t)ccol * DIM,
                  tid, lane, wrow, wcol, c);

    __nv_bfloat16* Eb = E + (size_t)z * SEQ * SEQ;
    float* rs = rowsum + z * SEQ;
    const int r0 = crow + wrow + (lane >> 2);
    const int c0 = ccol + wcol + (lane & 3) * 2;

    #pragma unroll
    for (int mt = 0; mt < 4; ++mt) {
        float s0 = 0.f, s1 = 0.f;
        #pragma unroll
        for (int nt = 0; nt < 4; ++nt) {
            float e0 = __expf(c[mt][nt][0] * alpha);
            float e1 = __expf(c[mt][nt][1] * alpha);
            float e2 = __expf(c[mt][nt][2] * alpha);
            float e3 = __expf(c[mt][nt][3] * alpha);
            s0 += e0 + e1;
            s1 += e2 + e3;
            *(__nv_bfloat162*)(Eb + (size_t)(r0 + mt * 16) * SEQ + c0 + nt * 8) =
                __floats2bfloat162_rn(e0, e1);
            *(__nv_bfloat162*)(Eb + (size_t)(r0 + mt * 16 + 8) * SEQ + c0 + nt * 8) =
                __floats2bfloat162_rn(e2, e3);
        }
        s0 += __shfl_xor_sync(0xFFFFFFFFu, s0, 1);
        s0 += __shfl_xor_sync(0xFFFFFFFFu, s0, 2);
        s1 += __shfl_xor_sync(0xFFFFFFFFu, s1, 1);
        s1 += __shfl_xor_sync(0xFFFFFFFFu, s1, 2);
        if ((lane & 3) == 0) {
            atomicAdd(&rs[r0 + mt * 16], s0);
            atomicAdd(&rs[r0 + mt * 16 + 8], s1);
        }
    }
}

// ============================================================================
// prep kernels
// ============================================================================

// x (fp32) -> xb (bf16), vectorized
__global__ void cvt_x(const float* __restrict__ x, __nv_bfloat16* __restrict__ xb,
                      int n4)
{
    int i = blockIdx.x * blockDim.x + threadIdx.x;
    for (; i < n4; i += gridDim.x * blockDim.x) {
        float4 v = ((const float4*)x)[i];
        uint2 o;
        __nv_bfloat162 p0 = __floats2bfloat162_rn(v.x, v.y);
        __nv_bfloat162 p1 = __floats2bfloat162_rn(v.z, v.w);
        o.x = *(uint32_t*)&p0; o.y = *(uint32_t*)&p1;
        ((uint2*)xb)[i] = o;
    }
}

// C[j][i] = bf16( sum_o A[j][o] * B[i][o] )  (512x512x512, fp32 accum)
__global__ __launch_bounds__(256) void mm_small_nt_bf16(
    const float* __restrict__ A, const float* __restrict__ B,
    __nv_bfloat16* __restrict__ C)
{
    __shared__ float sa[32][33], sbt[32][33];
    const int tx = threadIdx.x & 31, ty = threadIdx.x >> 5;  // 32 x 8
    const int j0 = blockIdx.y * 32, i0 = blockIdx.x * 32;
    float acc[4] = {};
    for (int o0 = 0; o0 < DIM; o0 += 32) {
        #pragma unroll
        for (int r = 0; r < 4; ++r) {
            sa[ty + 8 * r][tx]  = A[(size_t)(j0 + ty + 8 * r) * DIM + o0 + tx];
            sbt[ty + 8 * r][tx] = B[(size_t)(i0 + ty + 8 * r) * DIM + o0 + tx];
        }
        __syncthreads();
        #pragma unroll 8
        for (int o = 0; o < 32; ++o) {
            float bv = sbt[tx][o];
            #pragma unroll
            for (int r = 0; r < 4; ++r) acc[r] += sa[ty + 8 * r][o] * bv;
        }
        __syncthreads();
    }
    #pragma unroll
    for (int r = 0; r < 4; ++r)
        C[(size_t)(j0 + ty + 8 * r) * DIM + i0 + tx] = __float2bfloat16(acc[r]);
}

// ============================================================================
// zero accumulators (graph replay re-runs this before any atomics)
// ============================================================================
__global__ void zero_kernel(float* __restrict__ rowsum, float* __restrict__ colsum,
                            float* __restrict__ y, float* __restrict__ out)
{
    int i = blockIdx.x * blockDim.x + threadIdx.x;
    if (i < BATCH * SEQ) { rowsum[i] = 0.f; colsum[i] = 0.f; }
    if (i < BATCH * DIM) { y[i] = 0.f; out[i] = 0.f; }
}

__global__ void rowinv_kernel(const float* __restrict__ rowsum,
                              float* __restrict__ rowinv)
{
    int i = blockIdx.x * blockDim.x + threadIdx.x;
    if (i < BATCH * SEQ) rowinv[i] = 1.0f / rowsum[i];
}

// ============================================================================
// colsum[b][4m..4m+3] += sum_n E[b][n][4m..4m+3] * rowinv[b][n]
// 4 bf16 columns per thread via u64 loads.
// grid = (SEQ/1024, SEQ/128, BATCH), 256 threads
// ============================================================================
__global__ __launch_bounds__(256) void col_sum(
    const __nv_bfloat16* __restrict__ E, const float* __restrict__ rowinv,
    float* __restrict__ colsum)
{
    const int b = blockIdx.z;
    const int m4 = blockIdx.x * 256 + threadIdx.x;     // quad index
    const int n0 = blockIdx.y * 128;
    const uint2* Eb = (const uint2*)(E + (size_t)b * SEQ * SEQ);
    const float* ri = rowinv + b * SEQ;
    float a0 = 0.f, a1 = 0.f, a2 = 0.f, a3 = 0.f;
    #pragma unroll 8
    for (int n = n0; n < n0 + 128; ++n) {
        uint2 u = Eb[(size_t)n * (SEQ / 4) + m4];
        __nv_bfloat162 p0 = *(__nv_bfloat162*)&u.x;
        __nv_bfloat162 p1 = *(__nv_bfloat162*)&u.y;
        float r = ri[n];
        a0 += __bfloat162float(p0.x) * r;
        a1 += __bfloat162float(p0.y) * r;
        a2 += __bfloat162float(p1.x) * r;
        a3 += __bfloat162float(p1.y) * r;
    }
    float* cs = colsum + b * SEQ + 4 * m4;
    atomicAdd(cs + 0, a0);
    atomicAdd(cs + 1, a1);
    atomicAdd(cs + 2, a2);
    atomicAdd(cs + 3, a3);
}

// ============================================================================
// y[b][d] += sum_m colsum[b][m] * x[b][m][d]    (exact fp32 — random-sign
// sum: bf16 here does NOT average down, keep full precision)
// grid = (BATCH, SEQ/256), 512 threads
// ============================================================================
__global__ __launch_bounds__(512) void y_kernel(
    const float* __restrict__ x, const float* __restrict__ colsum,
    float* __restrict__ y)
{
    const int b = blockIdx.x;
    const int m0 = blockIdx.y * 256;
    const int d = threadIdx.x;
    const float* xb = x + (size_t)b * SEQ * DIM;
    const float* cb = colsum + b * SEQ;
    float acc = 0.f;
    #pragma unroll 4
    for (int m = m0; m < m0 + 256; ++m) acc += cb[m] * xb[(size_t)m * DIM + d];
    atomicAdd(&y[b * DIM + d], acc);
}

// ============================================================================
// out[b][o] += (1/SEQ) * sum_d y[b][d] * Wv[d][o]   (exact fp32)
// grid = (BATCH, 4), 512 threads; each block handles 128 d
// ============================================================================
__global__ __launch_bounds__(512) void out_kernel(
    const float* __restrict__ y, const float* __restrict__ Wv,
    float* __restrict__ out)
{
    __shared__ float ys[128];
    const int b = blockIdx.x;
    const int d0 = blockIdx.y * 128;
    const int o = threadIdx.x;
    if (o < 128) ys[o] = y[b * DIM + d0 + o];
    __syncthreads();
    float acc = 0.f;
    #pragma unroll 8
    for (int d = 0; d < 128; ++d)
        acc += ys[d] * Wv[(size_t)(d0 + d) * DIM + o];
    atomicAdd(&out[b * DIM + o], acc * (1.0f / SEQ));
}

// ============================================================================
extern "C" void kernel_launch(void* const* d_in, const int* in_sizes, int n_in,
                              void* d_out, int out_size)
{
    const float* x  = (const float*)d_in[0];
    const float* Wk = (const float*)d_in[1];
    const float* Wq = (const float*)d_in[2];
    const float* Wv = (const float*)d_in[3];
    float* out = (float*)d_out;

    float *RS, *RI, *CS, *Y;
    __nv_bfloat16 *MB, *TB, *XB, *E;
    cudaGetSymbolAddress((void**)&MB, g_Mb);
    cudaGetSymbolAddress((void**)&TB, g_Tb);
    cudaGetSymbolAddress((void**)&XB, g_xb);
    cudaGetSymbolAddress((void**)&E,  g_E);
    cudaGetSymbolAddress((void**)&RS, g_rowsum);
    cudaGetSymbolAddress((void**)&RI, g_rowinv);
    cudaGetSymbolAddress((void**)&CS, g_colsum);
    cudaGetSymbolAddress((void**)&Y,  g_y);

    cudaFuncSetAttribute(bf16_nt_bf16out, cudaFuncAttributeMaxDynamicSharedMemorySize, SMEM_H);
    cudaFuncSetAttribute(bf16_nt_exp,     cudaFuncAttributeMaxDynamicSharedMemorySize, SMEM_H);

    // 0. zero accumulators; Mb = bf16(Wq Wk^T transposed); xb = bf16(x)
    zero_kernel<<<(BATCH * SEQ + 255) / 256, 256>>>(RS, CS, Y, out);
    dim3 ms(DIM / 32, DIM / 32);
    mm_small_nt_bf16<<<ms, 256>>>(Wk, Wq, MB);  // MB[j][i] = sum_o Wk[j][o] Wq[i][o]
    cvt_x<<<2048, 256>>>(x, XB, BATCH * SEQ * DIM / 4);

    // 1. Tb = bf16(xb * Mb)  (bf16 mma, fp32 accum)
    dim3 gp(DIM / 128, (BATCH * SEQ) / 128, 1);   // (4, 256)
    bf16_nt_bf16out<<<gp, 256, SMEM_H>>>(XB, MB, TB);

    // 2. E[b] = exp(Tb[b] xb[b]^T / sqrt(512)) (bf16 mma) + rowsum atomics
    dim3 gs(SEQ / 128, SEQ / 128, BATCH);          // (16, 16, 16)
    bf16_nt_exp<<<gs, 256, SMEM_H>>>(TB, XB, E, RS, 1.0f / sqrtf((float)DIM));

    // 3. rowinv, colsum over E (4 cols/thread, u64 loads)
    rowinv_kernel<<<(BATCH * SEQ + 255) / 256, 256>>>(RS, RI);
    dim3 gc(SEQ / 1024, SEQ / 128, BATCH);         // (2, 16, 16)
    col_sum<<<gc, 256>>>(E, RI, CS);

    // 4. out = (1/N) * (colsum @ x) @ Wv   (exact fp32 GEMVs)
    dim3 gy(BATCH, SEQ / 256);
    y_kernel<<<gy, 512>>>(x, CS, Y);
    dim3 go(BATCH, DIM / 128);
    out_kernel<<<go, 512>>>(Y, Wv, out);
}

// round 16
// speedup vs baseline: 1.3295x; 1.3295x over previous
#include <cuda_runtime.h>
#include <cuda_bf16.h>
#include <stdint.h>
#include <math.h>

#define BATCH 16
#define SEQ   2048
#define DIM   512

// ---- scratch (static device globals; allocation-free per harness rules) ----
__device__ float g_Mt[DIM * DIM];                      // (Wq Wk^T)^T, tf32-rounded
__device__ __nv_bfloat16 g_Tb[BATCH * SEQ * DIM];      // (alpha * x*M) in bf16
__device__ __nv_bfloat16 g_xb[BATCH * SEQ * DIM];      // x in bf16
__device__ __nv_bfloat16 g_E[(size_t)BATCH * SEQ * SEQ];  // exp(scores), bf16
__device__ float g_rowsum[BATCH * SEQ];
__device__ float g_rowinv[BATCH * SEQ];
__device__ float g_colsum[BATCH * SEQ];
__device__ float g_y[BATCH * DIM];

// ---- helpers ---------------------------------------------------------------
__device__ __forceinline__ uint32_t f2t(float f) {
    uint32_t u;
    asm("cvt.rna.tf32.f32 %0, %1;" : "=r"(u) : "f"(f));
    return u;
}
__device__ __forceinline__ void mma8(float c[4], const uint32_t a[4],
                                     uint32_t b0, uint32_t b1) {
    asm volatile(
        "mma.sync.aligned.m16n8k8.row.col.f32.tf32.tf32.f32 "
        "{%0,%1,%2,%3}, {%4,%5,%6,%7}, {%8,%9}, {%0,%1,%2,%3};"
        : "+f"(c[0]), "+f"(c[1]), "+f"(c[2]), "+f"(c[3])
        : "r"(a[0]), "r"(a[1]), "r"(a[2]), "r"(a[3]), "r"(b0), "r"(b1));
}
__device__ __forceinline__ void mma16bf(float c[4], const uint32_t a[4],
                                        uint32_t b0, uint32_t b1) {
    asm volatile(
        "mma.sync.aligned.m16n8k16.row.col.f32.bf16.bf16.f32 "
        "{%0,%1,%2,%3}, {%4,%5,%6,%7}, {%8,%9}, {%0,%1,%2,%3};"
        : "+f"(c[0]), "+f"(c[1]), "+f"(c[2]), "+f"(c[3])
        : "r"(a[0]), "r"(a[1]), "r"(a[2]), "r"(a[3]), "r"(b0), "r"(b1));
}
__device__ __forceinline__ void ldsm4(uint32_t* r, uint32_t addr) {
    asm volatile("ldmatrix.sync.aligned.m8n8.x4.shared.b16 {%0,%1,%2,%3}, [%4];"
        : "=r"(r[0]), "=r"(r[1]), "=r"(r[2]), "=r"(r[3]) : "r"(addr));
}
__device__ __forceinline__ void cp16(uint32_t s, const void* g) {
    asm volatile("cp.async.cg.shared.global [%0], [%1], 16;"
        :: "r"(s), "l"(g) : "memory");
}
__device__ __forceinline__ uint32_t smem_u32(const void* p) {
    uint32_t a;
    asm("{ .reg .u64 t; cvta.to.shared.u64 t, %1; cvt.u32.u64 %0, t; }"
        : "=r"(a) : "l"(p));
    return a;
}

// ============================================================================
// TF32 NT GEMM (x fp32 raw, MT tf32-rounded), bf16 output: Tb = alpha * x*M
// 128x128 tile, BK=32 fp32, 3-stage cp.async. grid = (DIM/128, M/128)
// smem tile: 128 rows x 128B, soff = row*128 + ((ks ^ (row&7))<<4), ks=k/4
// ============================================================================
#define TILE_F   16384
#define STAGE_F  (2 * TILE_F)
#define SMEM_F   (3 * STAGE_F)   // 96 KB
#define NCH_F    (DIM / 32)      // 16

__device__ __forceinline__ void issue_tile_f(uint32_t sA, uint32_t sB,
    const float* __restrict__ gA, const float* __restrict__ gB, int tid)
{
    #pragma unroll
    for (int c = 0; c < 4; ++c) {
        int lin = c * 256 + tid;
        int row = lin >> 3, ks = lin & 7;
        uint32_t so = (uint32_t)(row * 128 + ((ks ^ (row & 7)) << 4));
        cp16(sA + so, gA + (size_t)row * DIM + ks * 4);
        cp16(sB + so, gB + (size_t)row * DIM + ks * 4);
    }
}

__global__ __launch_bounds__(256, 2) void tf32_nt_bf16out(
    const float* __restrict__ A, const float* __restrict__ B,
    __nv_bfloat16* __restrict__ C, float alpha)
{
    extern __shared__ char smem[];
    const uint32_t sb = smem_u32(smem);
    const int tid = threadIdx.x, lane = tid & 31, warp = tid >> 5;
    const int wrow = (warp >> 2) * 64, wcol = (warp & 3) * 32;
    const int crow = blockIdx.y * 128, ccol = blockIdx.x * 128;
    const float* Ab = A + (size_t)crow * DIM;
    const float* Bb = B + (size_t)ccol * DIM;

    const int local = lane & 7;
    const int halfA = (lane >> 3) & 1, kofA = lane >> 4;
    uint32_t arow[4]; int asw[4];
    #pragma unroll
    for (int mt = 0; mt < 4; ++mt) {
        int r = wrow + mt * 16 + halfA * 8 + local;
        arow[mt] = (uint32_t)(r * 128); asw[mt] = r & 7;
    }
    const int kofB = (lane >> 3) & 1, nhalf = (lane >> 4) & 1;
    uint32_t brow[2]; int bsw[2];
    #pragma unroll
    for (int bn = 0; bn < 2; ++bn) {
        int r = wcol + bn * 16 + nhalf * 8 + local;
        brow[bn] = (uint32_t)(r * 128); bsw[bn] = r & 7;
    }

    float c[4][4][4] = {};

    issue_tile_f(sb, sb + TILE_F, Ab, Bb, tid);
    asm volatile("cp.async.commit_group;" ::: "memory");
    issue_tile_f(sb + STAGE_F, sb + STAGE_F + TILE_F, Ab + 32, Bb + 32, tid);
    asm volatile("cp.async.commit_group;" ::: "memory");

    for (int ci = 0; ci < NCH_F; ++ci) {
        if (ci < NCH_F - 1)
            asm volatile("cp.async.wait_group 1;" ::: "memory");
        else
            asm volatile("cp.async.wait_group 0;" ::: "memory");
        __syncthreads();

        if (ci + 2 < NCH_F) {
            uint32_t st = sb + (uint32_t)(((ci + 2) % 3) * STAGE_F);
            issue_tile_f(st, st + TILE_F, Ab + (ci + 2) * 32, Bb + (ci + 2) * 32, tid);
            asm volatile("cp.async.commit_group;" ::: "memory");
        }

        const uint32_t Abase = sb + (uint32_t)((ci % 3) * STAGE_F);
        const uint32_t Bbase = Abase + TILE_F;
        #pragma unroll
        for (int kg = 0; kg < 4; ++kg) {
            uint32_t a[4][4], b[2][4];
            #pragma unroll
            for (int mt = 0; mt < 4; ++mt)
                ldsm4(a[mt], Abase + arow[mt] +
                      (uint32_t)((((kg * 2 + kofA) ^ asw[mt])) << 4));
            #pragma unroll
            for (int bn = 0; bn < 2; ++bn)
                ldsm4(b[bn], Bbase + brow[bn] +
                      (uint32_t)((((kg * 2 + kofB) ^ bsw[bn])) << 4));
            #pragma unroll
            for (int nt = 0; nt < 4; ++nt)
                #pragma unroll
                for (int mt = 0; mt < 4; ++mt)
                    mma8(c[mt][nt], a[mt], b[nt >> 1][(nt & 1) * 2],
                         b[nt >> 1][(nt & 1) * 2 + 1]);
        }
    }

    const int r0 = crow + wrow + (lane >> 2);
    const int c0 = ccol + wcol + (lane & 3) * 2;
    #pragma unroll
    for (int mt = 0; mt < 4; ++mt) {
        #pragma unroll
        for (int nt = 0; nt < 4; ++nt) {
            *(__nv_bfloat162*)(C + (size_t)(r0 + mt * 16) * DIM + c0 + nt * 8) =
                __floats2bfloat162_rn(c[mt][nt][0] * alpha, c[mt][nt][1] * alpha);
            *(__nv_bfloat162*)(C + (size_t)(r0 + mt * 16 + 8) * DIM + c0 + nt * 8) =
                __floats2bfloat162_rn(c[mt][nt][2] * alpha, c[mt][nt][3] * alpha);
        }
    }
}

// ============================================================================
// BF16 NT scores GEMM + fused exp epilogue (alpha pre-folded into Tb):
//   E[b][n][m] = exp(Tb[b][n]·xb[b][m])  (bf16), rowsum atomics.
// m16n8k16, BK=64 (8 chunks), 3-stage cp.async. grid=(SEQ/128,SEQ/128,BATCH)
// smem tile: 128 rows x 64 bf16 (128B); soff = row*128 + ((ks ^ (row&7))<<4)
// ============================================================================
#define TILE_H   16384
#define STAGE_H  (2 * TILE_H)
#define SMEM_H   (3 * STAGE_H)   // 96 KB
#define NCH_H    (DIM / 64)      // 8

__device__ __forceinline__ void issue_tile_h(uint32_t sA, uint32_t sB,
    const __nv_bfloat16* __restrict__ gA, const __nv_bfloat16* __restrict__ gB,
    int tid)
{
    #pragma unroll
    for (int c = 0; c < 4; ++c) {
        int lin = c * 256 + tid;
        int row = lin >> 3, ks = lin & 7;
        uint32_t so = (uint32_t)(row * 128 + ((ks ^ (row & 7)) << 4));
        cp16(sA + so, gA + (size_t)row * DIM + ks * 8);
        cp16(sB + so, gB + (size_t)row * DIM + ks * 8);
    }
}

__global__ __launch_bounds__(256, 2) void bf16_nt_exp(
    const __nv_bfloat16* __restrict__ A, const __nv_bfloat16* __restrict__ B,
    __nv_bfloat16* __restrict__ E, float* __restrict__ rowsum)
{
    extern __shared__ char smem[];
    const uint32_t sb = smem_u32(smem);
    const int tid = threadIdx.x, lane = tid & 31, warp = tid >> 5;
    const int wrow = (warp >> 2) * 64, wcol = (warp & 3) * 32;
    const int z = blockIdx.z;
    const int crow = blockIdx.y * 128, ccol = blockIdx.x * 128;
    const __nv_bfloat16* Ab = A + (size_t)z * SEQ * DIM + (size_t)crow * DIM;
    const __nv_bfloat16* Bb = B + (size_t)z * SEQ * DIM + (size_t)ccol * DIM;

    const int local = lane & 7;
    const int rhalf = (lane >> 3) & 1;   // row-half within 16
    const int kof   = lane >> 4;         // kseg offset (0/1)
    uint32_t arow[4]; int asw[4];
    #pragma unroll
    for (int mt = 0; mt < 4; ++mt) {
        int r = wrow + mt * 16 + rhalf * 8 + local;
        arow[mt] = (uint32_t)(r * 128); asw[mt] = r & 7;
    }
    uint32_t brow[2]; int bsw[2];
    #pragma unroll
    for (int bn = 0; bn < 2; ++bn) {
        int r = wcol + bn * 16 + rhalf * 8 + local;
        brow[bn] = (uint32_t)(r * 128); bsw[bn] = r & 7;
    }

    float c[4][4][4] = {};

    issue_tile_h(sb, sb + TILE_H, Ab, Bb, tid);
    asm volatile("cp.async.commit_group;" ::: "memory");
    issue_tile_h(sb + STAGE_H, sb + STAGE_H + TILE_H, Ab + 64, Bb + 64, tid);
    asm volatile("cp.async.commit_group;" ::: "memory");

    for (int ci = 0; ci < NCH_H; ++ci) {
        if (ci < NCH_H - 1)
            asm volatile("cp.async.wait_group 1;" ::: "memory");
        else
            asm volatile("cp.async.wait_group 0;" ::: "memory");
        __syncthreads();

        if (ci + 2 < NCH_H) {
            uint32_t st = sb + (uint32_t)(((ci + 2) % 3) * STAGE_H);
            issue_tile_h(st, st + TILE_H, Ab + (ci + 2) * 64, Bb + (ci + 2) * 64, tid);
            asm volatile("cp.async.commit_group;" ::: "memory");
        }

        const uint32_t Abase = sb + (uint32_t)((ci % 3) * STAGE_H);
        const uint32_t Bbase = Abase + TILE_H;
        #pragma unroll
        for (int ks = 0; ks < 4; ++ks) {          // 4 k16-steps per BK=64
            const int kseg = ks * 2 + kof;
            uint32_t a[4][4], b[2][4];
            #pragma unroll
            for (int mt = 0; mt < 4; ++mt)
                ldsm4(a[mt], Abase + arow[mt] +
                      (uint32_t)(((kseg ^ asw[mt])) << 4));
            #pragma unroll
            for (int bn = 0; bn < 2; ++bn)
                ldsm4(b[bn], Bbase + brow[bn] +
                      (uint32_t)(((kseg ^ bsw[bn])) << 4));
            #pragma unroll
            for (int nt = 0; nt < 4; ++nt) {
                const int bn = nt >> 1, h = nt & 1;
                #pragma unroll
                for (int mt = 0; mt < 4; ++mt)
                    mma16bf(c[mt][nt], a[mt], b[bn][h], b[bn][h + 2]);
            }
        }
    }

    __nv_bfloat16* Eb = E + (size_t)z * SEQ * SEQ;
    float* rs = rowsum + z * SEQ;
    const int r0 = crow + wrow + (lane >> 2);
    const int c0 = ccol + wcol + (lane & 3) * 2;

    #pragma unroll
    for (int mt = 0; mt < 4; ++mt) {
        float s0 = 0.f, s1 = 0.f;
        #pragma unroll
        for (int nt = 0; nt < 4; ++nt) {
            float e0 = __expf(c[mt][nt][0]);
            float e1 = __expf(c[mt][nt][1]);
            float e2 = __expf(c[mt][nt][2]);
            float e3 = __expf(c[mt][nt][3]);
            s0 += e0 + e1;
            s1 += e2 + e3;
            *(__nv_bfloat162*)(Eb + (size_t)(r0 + mt * 16) * SEQ + c0 + nt * 8) =
                __floats2bfloat162_rn(e0, e1);
            *(__nv_bfloat162*)(Eb + (size_t)(r0 + mt * 16 + 8) * SEQ + c0 + nt * 8) =
                __floats2bfloat162_rn(e2, e3);
        }
        // reduce across the 4 lanes sharing a row (lane & 3)
        s0 += __shfl_xor_sync(0xFFFFFFFFu, s0, 1);
        s0 += __shfl_xor_sync(0xFFFFFFFFu, s0, 2);
        s1 += __shfl_xor_sync(0xFFFFFFFFu, s1, 1);
        s1 += __shfl_xor_sync(0xFFFFFFFFu, s1, 2);
        if ((lane & 3) == 0) {
            atomicAdd(&rs[r0 + mt * 16], s0);
            atomicAdd(&rs[r0 + mt * 16 + 8], s1);
        }
    }
}

// ============================================================================
// prep kernels
// ============================================================================

// x (fp32) -> xb (bf16), vectorized
__global__ void cvt_x(const float* __restrict__ x, __nv_bfloat16* __restrict__ xb,
                      int n4)
{
    int i = blockIdx.x * blockDim.x + threadIdx.x;
    for (; i < n4; i += gridDim.x * blockDim.x) {
        float4 v = ((const float4*)x)[i];
        uint2 o;
        __nv_bfloat162 p0 = __floats2bfloat162_rn(v.x, v.y);
        __nv_bfloat162 p1 = __floats2bfloat162_rn(v.z, v.w);
        o.x = *(uint32_t*)&p0; o.y = *(uint32_t*)&p1;
        ((uint2*)xb)[i] = o;
    }
}

// C[j][i] = sum_o A[j][o] * B[i][o]  (512x512x512, fp32, tf32-rounded output)
__global__ __launch_bounds__(256) void mm_small_nt(
    const float* __restrict__ A, const float* __restrict__ B, float* __restrict__ C)
{
    __shared__ float sa[32][33], sbt[32][33];
    const int tx = threadIdx.x & 31, ty = threadIdx.x >> 5;  // 32 x 8
    const int j0 = blockIdx.y * 32, i0 = blockIdx.x * 32;
    float acc[4] = {};
    for (int o0 = 0; o0 < DIM; o0 += 32) {
        #pragma unroll
        for (int r = 0; r < 4; ++r) {
            sa[ty + 8 * r][tx]  = A[(size_t)(j0 + ty + 8 * r) * DIM + o0 + tx];
            sbt[ty + 8 * r][tx] = B[(size_t)(i0 + ty + 8 * r) * DIM + o0 + tx];
        }
        __syncthreads();
        #pragma unroll 8
        for (int o = 0; o < 32; ++o) {
            float bv = sbt[tx][o];
            #pragma unroll
            for (int r = 0; r < 4; ++r) acc[r] += sa[ty + 8 * r][o] * bv;
        }
        __syncthreads();
    }
    #pragma unroll
    for (int r = 0; r < 4; ++r)
        C[(size_t)(j0 + ty + 8 * r) * DIM + i0 + tx] =
            __uint_as_float(f2t(acc[r]));
}

// ============================================================================
// zero accumulators (graph replay re-runs this before any atomics)
// ============================================================================
__global__ void zero_kernel(float* __restrict__ rowsum, float* __restrict__ colsum,
                            float* __restrict__ y, float* __restrict__ out)
{
    int i = blockIdx.x * blockDim.x + threadIdx.x;
    if (i < BATCH * SEQ) { rowsum[i] = 0.f; colsum[i] = 0.f; }
    if (i < BATCH * DIM) { y[i] = 0.f; out[i] = 0.f; }
}

__global__ void rowinv_kernel(const float* __restrict__ rowsum,
                              float* __restrict__ rowinv)
{
    int i = blockIdx.x * blockDim.x + threadIdx.x;
    if (i < BATCH * SEQ) rowinv[i] = 1.0f / rowsum[i];
}

// ============================================================================
// colsum[b][4m..4m+3] += sum_n E[b][n][4m..4m+3] * rowinv[b][n]
// 4 bf16 columns per thread via u64 loads.
// grid = (SEQ/1024, SEQ/128, BATCH), 256 threads
// ============================================================================
__global__ __launch_bounds__(256) void col_sum(
    const __nv_bfloat16* __restrict__ E, const float* __restrict__ rowinv,
    float* __restrict__ colsum)
{
    const int b = blockIdx.z;
    const int m4 = blockIdx.x * 256 + threadIdx.x;     // quad index
    const int n0 = blockIdx.y * 128;
    const uint2* Eb = (const uint2*)(E + (size_t)b * SEQ * SEQ);
    const float* ri = rowinv + b * SEQ;
    float a0 = 0.f, a1 = 0.f, a2 = 0.f, a3 = 0.f;
    #pragma unroll 8
    for (int n = n0; n < n0 + 128; ++n) {
        uint2 u = Eb[(size_t)n * (SEQ / 4) + m4];
        __nv_bfloat162 p0 = *(__nv_bfloat162*)&u.x;
        __nv_bfloat162 p1 = *(__nv_bfloat162*)&u.y;
        float r = ri[n];
        a0 += __bfloat162float(p0.x) * r;
        a1 += __bfloat162float(p0.y) * r;
        a2 += __bfloat162float(p1.x) * r;
        a3 += __bfloat162float(p1.y) * r;
    }
    float* cs = colsum + b * SEQ + 4 * m4;
    atomicAdd(cs + 0, a0);
    atomicAdd(cs + 1, a1);
    atomicAdd(cs + 2, a2);
    atomicAdd(cs + 3, a3);
}

// ============================================================================
// y[b][d] += sum_m colsum[b][m] * x[b][m][d]   (exact fp32 — random-sign sum,
// bf16 here does NOT average down; keep full precision)
// grid = (BATCH, SEQ/256), 512 threads
// ============================================================================
__global__ __launch_bounds__(512) void y_kernel(
    const float* __restrict__ x, const float* __restrict__ colsum,
    float* __restrict__ y)
{
    const int b = blockIdx.x;
    const int m0 = blockIdx.y * 256;
    const int d = threadIdx.x;
    const float* xb = x + (size_t)b * SEQ * DIM;
    const float* cb = colsum + b * SEQ;
    float acc = 0.f;
    #pragma unroll 4
    for (int m = m0; m < m0 + 256; ++m) acc += cb[m] * xb[(size_t)m * DIM + d];
    atomicAdd(&y[b * DIM + d], acc);
}

// ============================================================================
// out[b][o] += (1/SEQ) * sum_d y[b][d] * Wv[d][o]   (exact fp32)
// grid = (BATCH, 4), 512 threads; each block handles 128 d
// ============================================================================
__global__ __launch_bounds__(512) void out_kernel(
    const float* __restrict__ y, const float* __restrict__ Wv,
    float* __restrict__ out)
{
    __shared__ float ys[128];
    const int b = blockIdx.x;
    const int d0 = blockIdx.y * 128;
    const int o = threadIdx.x;
    if (o < 128) ys[o] = y[b * DIM + d0 + o];
    __syncthreads();
    float acc = 0.f;
    #pragma unroll 8
    for (int d = 0; d < 128; ++d)
        acc += ys[d] * Wv[(size_t)(d0 + d) * DIM + o];
    atomicAdd(&out[b * DIM + o], acc * (1.0f / SEQ));
}

// ============================================================================
extern "C" void kernel_launch(void* const* d_in, const int* in_sizes, int n_in,
                              void* d_out, int out_size)
{
    const float* x  = (const float*)d_in[0];
    const float* Wk = (const float*)d_in[1];
    const float* Wq = (const float*)d_in[2];
    const float* Wv = (const float*)d_in[3];
    float* out = (float*)d_out;

    float *MT, *RS, *RI, *CS, *Y;
    __nv_bfloat16 *TB, *XB, *E;
    cudaGetSymbolAddress((void**)&MT, g_Mt);
    cudaGetSymbolAddress((void**)&TB, g_Tb);
    cudaGetSymbolAddress((void**)&XB, g_xb);
    cudaGetSymbolAddress((void**)&E,  g_E);
    cudaGetSymbolAddress((void**)&RS, g_rowsum);
    cudaGetSymbolAddress((void**)&RI, g_rowinv);
    cudaGetSymbolAddress((void**)&CS, g_colsum);
    cudaGetSymbolAddress((void**)&Y,  g_y);

    cudaFuncSetAttribute(tf32_nt_bf16out, cudaFuncAttributeMaxDynamicSharedMemorySize, SMEM_F);
    cudaFuncSetAttribute(bf16_nt_exp,     cudaFuncAttributeMaxDynamicSharedMemorySize, SMEM_H);

    // 0. zero accumulators; MT = tf32(Wq Wk^T transposed); xb = bf16(x)
    zero_kernel<<<(BATCH * SEQ + 255) / 256, 256>>>(RS, CS, Y, out);
    dim3 ms(DIM / 32, DIM / 32);
    mm_small_nt<<<ms, 256>>>(Wk, Wq, MT);   // MT[j][i] = sum_o Wk[j][o] Wq[i][o]
    cvt_x<<<2048, 256>>>(x, XB, BATCH * SEQ * DIM / 4);

    // 1. Tb = bf16(alpha * x * M)  (tf32 mma: x raw fp32, MT tf32-rounded)
    dim3 gp(DIM / 128, (BATCH * SEQ) / 128, 1);   // (4, 256)
    tf32_nt_bf16out<<<gp, 256, SMEM_F>>>(x, MT, TB, 1.0f / sqrtf((float)DIM));

    // 2. E[b] = exp(Tb[b] xb[b]^T) (bf16 mma; alpha pre-folded) + rowsum
    dim3 gs(SEQ / 128, SEQ / 128, BATCH);          // (16, 16, 16)
    bf16_nt_exp<<<gs, 256, SMEM_H>>>(TB, XB, E, RS);

    // 3. rowinv, colsum over E (4 cols/thread, u64 loads)
    rowinv_kernel<<<(BATCH * SEQ + 255) / 256, 256>>>(RS, RI);
    dim3 gc(SEQ / 1024, SEQ / 128, BATCH);         // (2, 16, 16)
    col_sum<<<gc, 256>>>(E, RI, CS);

    // 4. out = (1/N) * (colsum @ x) @ Wv   (exact fp32 GEMVs)
    dim3 gy(BATCH, SEQ / 256);
    y_kernel<<<gy, 512>>>(x, CS, Y);
    dim3 go(BATCH, DIM / 128);
    out_kernel<<<go, 512>>>(Y, Wv, out);
}